// round 11
// baseline (speedup 1.0000x reference)
#include <cuda_runtime.h>
#include <cuda_bf16.h>

// out[b,0,h,w] = sum_c x[b,c,h,w] * wq[c] + bias
// x: (8,128,512,512) f32, W: 128 f32 (quant-dequant to int8 grid), b: 1 f32
// Pure HBM-bound streaming reduction over channel dim.
// R3: 172.8us @ DRAM 80.3% (2048 blocks, ~2 waves).
// R6: 166.2us @ DRAM 84.8% (1024 blocks, regs=42 -> ragged wave).
// R9: 159.8us @ DRAM 85.8% (fused, 36-reg cap, single wave; L2 at the
//     ~6300 B/cyc path-independent LTS cap -> near chip streaming ceiling).
// R10: warp-local weight quant (no smem, no barriers) so every warp starts
//      streaming x immediately; kills the per-block prologue ramp.

#define C_CH   128
#define HW     (512 * 512)        // 262144 elems per plane
#define HW4    (HW / 4)           // 65536 float4 per plane
#define BATCH  8
#define NBLK   1024               // <= 1064 (=152 SMs * 7 blocks) -> one wave
#define NTILE  2                  // 2048 tiles total / NBLK
#define FULLM  0xffffffffu

__global__ __launch_bounds__(256, 7) void channel_reduce_fused_kernel(
    const float* __restrict__ x,
    const float* __restrict__ W,
    const float* __restrict__ bias,
    float* __restrict__ out)
{
    int t    = threadIdx.x;
    int lane = t & 31;

    // --- warp-local quant-dequant: lane l holds channels 4l..4l+3 in regs.
    float4 wv = reinterpret_cast<const float4*>(W)[lane];   // 32 lanes x 4 = 128
    float m = fmaxf(fmaxf(fabsf(wv.x), fabsf(wv.y)),
                    fmaxf(fabsf(wv.z), fabsf(wv.w)));
    #pragma unroll
    for (int s = 16; s > 0; s >>= 1)
        m = fmaxf(m, __shfl_xor_sync(FULLM, m, s));
    float scale = m / 127.0f;
    float inv   = 1.0f / scale;
    float wq[4];
    wq[0] = fminf(fmaxf(rintf(wv.x * inv), -127.0f), 127.0f) * scale;
    wq[1] = fminf(fmaxf(rintf(wv.y * inv), -127.0f), 127.0f) * scale;
    wq[2] = fminf(fmaxf(rintf(wv.z * inv), -127.0f), 127.0f) * scale;
    wq[3] = fminf(fmaxf(rintf(wv.w * inv), -127.0f), 127.0f) * scale;

    float bb = bias[0];

    // --- streaming channel reduction, 2 tiles per block, sequential.
    #pragma unroll
    for (int tile = 0; tile < NTILE; ++tile) {
        int o4 = (blockIdx.x + tile * NBLK) * blockDim.x + t;  // 0..524287
        int b  = o4 >> 16;                    // o4 / HW4
        int s4 = o4 & (HW4 - 1);              // o4 % HW4

        const float4* xp = reinterpret_cast<const float4*>(x)
                         + (size_t)b * (C_CH * HW4) + s4;

        float ax0 = 0.f, ay0 = 0.f, az0 = 0.f, aw0 = 0.f;
        float ax1 = 0.f, ay1 = 0.f, az1 = 0.f, aw1 = 0.f;

        #pragma unroll 8
        for (int c = 0; c < C_CH / 2; ++c) {
            float4 v0 = __ldg(xp + (size_t)c * HW4);
            float4 v1 = __ldg(xp + (size_t)(c + C_CH / 2) * HW4);
            // channel c lives in reg (c&3) of lane (c>>2); c+64 -> lane+16.
            float w0 = __shfl_sync(FULLM, wq[c & 3], (c >> 2));
            float w1 = __shfl_sync(FULLM, wq[c & 3], (c >> 2) + 16);
            ax0 = fmaf(v0.x, w0, ax0);
            ay0 = fmaf(v0.y, w0, ay0);
            az0 = fmaf(v0.z, w0, az0);
            aw0 = fmaf(v0.w, w0, aw0);
            ax1 = fmaf(v1.x, w1, ax1);
            ay1 = fmaf(v1.y, w1, ay1);
            az1 = fmaf(v1.z, w1, az1);
            aw1 = fmaf(v1.w, w1, aw1);
        }

        float4 r;
        r.x = ax0 + ax1 + bb;
        r.y = ay0 + ay1 + bb;
        r.z = az0 + az1 + bb;
        r.w = aw0 + aw1 + bb;
        reinterpret_cast<float4*>(out)[o4] = r;
    }
}

extern "C" void kernel_launch(void* const* d_in, const int* in_sizes, int n_in,
                              void* d_out, int out_size) {
    const float* x    = (const float*)d_in[0];
    const float* W    = (const float*)d_in[1];
    const float* bias = (const float*)d_in[2];
    float* out        = (float*)d_out;

    channel_reduce_fused_kernel<<<NBLK, 256>>>(x, W, bias, out);
}

// round 12
// speedup vs baseline: 1.1968x; 1.1968x over previous
#include <cuda_runtime.h>
#include <cuda_bf16.h>

// out[b,0,h,w] = sum_c x[b,c,h,w] * wq[c] + bias
// x: (8,128,512,512) f32, W: 128 f32 (quant-dequant to int8 grid), b: 1 f32
// Pure HBM-bound streaming reduction over channel dim.
// R3:  172.8us @ DRAM 80.3% (2048 blocks, ~2 waves).
// R6:  166.2us @ DRAM 84.8% (1024 blocks, regs=42 -> ragged wave).
// R9:  159.8us @ DRAM 85.8% (fused quant, smem weights, 36-reg single wave).
// R11: 189.3us REGRESSION — shfl-based weights throttled LDG issue. Reverted.
// R12: R9 body + __ldcs/__stcs streaming hints (x has zero reuse).

#define C_CH   128
#define HW     (512 * 512)        // 262144 elems per plane
#define HW4    (HW / 4)           // 65536 float4 per plane
#define BATCH  8
#define NBLK   1024               // <= 1064 (=152 SMs * 7 blocks) -> one wave
#define NTILE  2                  // 2048 tiles total / NBLK

__global__ __launch_bounds__(256, 7) void channel_reduce_fused_kernel(
    const float* __restrict__ x,
    const float* __restrict__ W,
    const float* __restrict__ bias,
    float* __restrict__ out)
{
    __shared__ float ws[C_CH];
    __shared__ float red[C_CH];
    int t = threadIdx.x;

    // --- inline quant-dequant: scale = max|W|/127; wq = clip(rint(W/scale))*scale
    float w = 0.f;
    if (t < C_CH) {
        w = W[t];
        red[t] = fabsf(w);
    }
    __syncthreads();
    #pragma unroll
    for (int s = 64; s > 0; s >>= 1) {
        if (t < s) red[t] = fmaxf(red[t], red[t + s]);
        __syncthreads();
    }
    if (t < C_CH) {
        float scale = red[0] / 127.0f;
        float q = rintf(w / scale);          // round-half-even, matches jnp.round
        q = fminf(fmaxf(q, -127.0f), 127.0f);
        ws[t] = q * scale;
    }
    float bb = bias[0];
    __syncthreads();

    // --- streaming channel reduction, 2 tiles per block, sequential
    #pragma unroll
    for (int tile = 0; tile < NTILE; ++tile) {
        int o4 = (blockIdx.x + tile * NBLK) * blockDim.x + t;  // 0..524287
        int b  = o4 >> 16;                    // o4 / HW4
        int s4 = o4 & (HW4 - 1);              // o4 % HW4

        const float4* xp = reinterpret_cast<const float4*>(x)
                         + (size_t)b * (C_CH * HW4) + s4;

        float ax0 = 0.f, ay0 = 0.f, az0 = 0.f, aw0 = 0.f;
        float ax1 = 0.f, ay1 = 0.f, az1 = 0.f, aw1 = 0.f;

        #pragma unroll 8
        for (int c = 0; c < C_CH / 2; ++c) {
            float4 v0 = __ldcs(xp + (size_t)c * HW4);            // evict-first stream
            float4 v1 = __ldcs(xp + (size_t)(c + C_CH / 2) * HW4);
            float w0 = ws[c];                                    // broadcast LDS
            float w1 = ws[c + C_CH / 2];
            ax0 = fmaf(v0.x, w0, ax0);
            ay0 = fmaf(v0.y, w0, ay0);
            az0 = fmaf(v0.z, w0, az0);
            aw0 = fmaf(v0.w, w0, aw0);
            ax1 = fmaf(v1.x, w1, ax1);
            ay1 = fmaf(v1.y, w1, ay1);
            az1 = fmaf(v1.z, w1, az1);
            aw1 = fmaf(v1.w, w1, aw1);
        }

        float4 r;
        r.x = ax0 + ax1 + bb;
        r.y = ay0 + ay1 + bb;
        r.z = az0 + az1 + bb;
        r.w = aw0 + aw1 + bb;
        __stcs(reinterpret_cast<float4*>(out) + o4, r);
    }
}

extern "C" void kernel_launch(void* const* d_in, const int* in_sizes, int n_in,
                              void* d_out, int out_size) {
    const float* x    = (const float*)d_in[0];
    const float* W    = (const float*)d_in[1];
    const float* bias = (const float*)d_in[2];
    float* out        = (float*)d_out;

    channel_reduce_fused_kernel<<<NBLK, 256>>>(x, W, bias, out);
}

// round 13
// speedup vs baseline: 1.2106x; 1.0115x over previous
#include <cuda_runtime.h>
#include <cuda_bf16.h>

// out[b,0,h,w] = sum_c x[b,c,h,w] * wq[c] + bias
// x: (8,128,512,512) f32, W: 128 f32 (quant-dequant to int8 grid), b: 1 f32
// Pure HBM-bound streaming reduction over channel dim.
// R3:  172.8us @ DRAM 80.3% (2048 blocks, ~2 waves).
// R6:  166.2us @ DRAM 84.8% (1024 blocks, regs=42 -> ragged wave).
// R9:  159.8us @ DRAM 85.8% (fused quant, smem weights, 36-reg single wave).
// R11: 189.3us REGRESSION — shfl in hot loop throttled LDG issue. Reverted.
// R12: 158.2us @ DRAM 84.6% (__ldcs/__stcs). At ~6.7-6.8 TB/s = chip ceiling.
// R13: barrier-free prologue — per-warp weight quant into private smem
//      (shfl reduce + STS, zero __syncthreads) so streaming starts ~60cyc in.

#define C_CH   128
#define HW     (512 * 512)        // 262144 elems per plane
#define HW4    (HW / 4)           // 65536 float4 per plane
#define BATCH  8
#define NBLK   1024               // <= 1064 (=152 SMs * 7 blocks) -> one wave
#define NTILE  2                  // 2048 tiles total / NBLK
#define NWARP  8
#define FULLM  0xffffffffu

__global__ __launch_bounds__(256, 7) void channel_reduce_fused_kernel(
    const float* __restrict__ x,
    const float* __restrict__ W,
    const float* __restrict__ bias,
    float* __restrict__ out)
{
    // Per-warp private copy of the dequantized weights: no cross-warp sync.
    __shared__ float ws[NWARP][C_CH];

    int t    = threadIdx.x;
    int wid  = t >> 5;
    int lane = t & 31;

    float bb = bias[0];

    // --- warp-local quant-dequant (no barriers): lane l owns channels 4l..4l+3
    float4 wv = reinterpret_cast<const float4*>(W)[lane];   // 32 lanes x 4 = 128
    float m = fmaxf(fmaxf(fabsf(wv.x), fabsf(wv.y)),
                    fmaxf(fabsf(wv.z), fabsf(wv.w)));
    #pragma unroll
    for (int s = 16; s > 0; s >>= 1)
        m = fmaxf(m, __shfl_xor_sync(FULLM, m, s));
    float scale = m / 127.0f;
    float inv   = 127.0f / m;
    float4 q;
    q.x = fminf(fmaxf(rintf(wv.x * inv), -127.0f), 127.0f) * scale;
    q.y = fminf(fmaxf(rintf(wv.y * inv), -127.0f), 127.0f) * scale;
    q.z = fminf(fmaxf(rintf(wv.z * inv), -127.0f), 127.0f) * scale;
    q.w = fminf(fmaxf(rintf(wv.w * inv), -127.0f), 127.0f) * scale;
    // STS.128 into this warp's region; same-warp LDS below is program-ordered.
    reinterpret_cast<float4*>(ws[wid])[lane] = q;
    __syncwarp();

    // --- streaming channel reduction, 2 tiles per block, sequential
    #pragma unroll
    for (int tile = 0; tile < NTILE; ++tile) {
        int o4 = (blockIdx.x + tile * NBLK) * blockDim.x + t;  // 0..524287
        int b  = o4 >> 16;                    // o4 / HW4
        int s4 = o4 & (HW4 - 1);              // o4 % HW4

        const float4* xp = reinterpret_cast<const float4*>(x)
                         + (size_t)b * (C_CH * HW4) + s4;

        float ax0 = 0.f, ay0 = 0.f, az0 = 0.f, aw0 = 0.f;
        float ax1 = 0.f, ay1 = 0.f, az1 = 0.f, aw1 = 0.f;

        #pragma unroll 8
        for (int c = 0; c < C_CH / 2; ++c) {
            float4 v0 = __ldcs(xp + (size_t)c * HW4);            // evict-first
            float4 v1 = __ldcs(xp + (size_t)(c + C_CH / 2) * HW4);
            float w0 = ws[wid][c];                               // broadcast LDS
            float w1 = ws[wid][c + C_CH / 2];
            ax0 = fmaf(v0.x, w0, ax0);
            ay0 = fmaf(v0.y, w0, ay0);
            az0 = fmaf(v0.z, w0, az0);
            aw0 = fmaf(v0.w, w0, aw0);
            ax1 = fmaf(v1.x, w1, ax1);
            ay1 = fmaf(v1.y, w1, ay1);
            az1 = fmaf(v1.z, w1, az1);
            aw1 = fmaf(v1.w, w1, aw1);
        }

        float4 r;
        r.x = ax0 + ax1 + bb;
        r.y = ay0 + ay1 + bb;
        r.z = az0 + az1 + bb;
        r.w = aw0 + aw1 + bb;
        __stcs(reinterpret_cast<float4*>(out) + o4, r);
    }
}

extern "C" void kernel_launch(void* const* d_in, const int* in_sizes, int n_in,
                              void* d_out, int out_size) {
    const float* x    = (const float*)d_in[0];
    const float* W    = (const float*)d_in[1];
    const float* bias = (const float*)d_in[2];
    float* out        = (float*)d_out;

    channel_reduce_fused_kernel<<<NBLK, 256>>>(x, W, bias, out);
}